// round 9
// baseline (speedup 1.0000x reference)
#include <cuda_runtime.h>
#include <cuda_bf16.h>
#include <stdint.h>
#include <math.h>

#define B_    64
#define T_    12
#define N_    800
#define CIN_  2
#define H_    64
#define HOR_  12
#define TC_H  2
#define KAPPA_ 0.05f
#define NB    (N_*B_)
#define CF0   208
#define CF1   384
#define MPAD  1664

// ---------------- device scratch ----------------
__device__ float g_A2[1600*800];
__device__ __align__(16) __nv_bfloat16 g_A2h[MPAD*800];
__device__ __align__(16) __nv_bfloat16 g_A2l[MPAD*800];
__device__ float g_EMBX[B_*T_*N_*TC_H];
__device__ float g_EMBY[B_*HOR_*N_*TC_H];
__device__ float g_H0[NB*H_];
__device__ float g_H1[NB*H_];
__device__ float g_UR[NB*128];
__device__ float g_GO[NB*CIN_];
__device__ float g_Q [B_*8];
__device__ float g_ATTM[B_*N_*8];
// layer-0 feature buffers (stride CF0) and layer-1 (stride CF1), gate(F)/cand(FC)
__device__ __align__(16) __nv_bfloat16 g_F0h [NB*CF0];
__device__ __align__(16) __nv_bfloat16 g_F0l [NB*CF0];
__device__ __align__(16) __nv_bfloat16 g_FC0h[NB*CF0];
__device__ __align__(16) __nv_bfloat16 g_FC0l[NB*CF0];
__device__ __align__(16) __nv_bfloat16 g_F1h [NB*CF1];
__device__ __align__(16) __nv_bfloat16 g_F1l [NB*CF1];
__device__ __align__(16) __nv_bfloat16 g_FC1h[NB*CF1];
__device__ __align__(16) __nv_bfloat16 g_FC1l[NB*CF1];
__device__ __align__(16) __nv_bfloat16 g_WGh[4][384*128];
__device__ __align__(16) __nv_bfloat16 g_WGl[4][384*128];
__device__ __align__(16) __nv_bfloat16 g_WCh[4][384*64];
__device__ __align__(16) __nv_bfloat16 g_WCl[4][384*64];

// ---------------- helpers ----------------
__device__ __forceinline__ unsigned su(void* p) {
    return (unsigned)__cvta_generic_to_shared(p);
}
__device__ __forceinline__ void cp16(void* dst, const void* src) {
    asm volatile("cp.async.ca.shared.global [%0],[%1],16;" :: "r"(su(dst)), "l"(src));
}
__device__ __forceinline__ void cp8(void* dst, const void* src) {
    asm volatile("cp.async.ca.shared.global [%0],[%1],8;" :: "r"(su(dst)), "l"(src));
}
__device__ __forceinline__ void cp_commit() {
    asm volatile("cp.async.commit_group;");
}
__device__ __forceinline__ void ldsm_x4(unsigned* r, unsigned addr) {
    asm volatile("ldmatrix.sync.aligned.m8n8.x4.shared.b16 {%0,%1,%2,%3},[%4];"
        : "=r"(r[0]),"=r"(r[1]),"=r"(r[2]),"=r"(r[3]) : "r"(addr));
}
__device__ __forceinline__ void ldsm_x2t(unsigned* r, unsigned addr) {
    asm volatile("ldmatrix.sync.aligned.m8n8.x2.trans.shared.b16 {%0,%1},[%2];"
        : "=r"(r[0]),"=r"(r[1]) : "r"(addr));
}
__device__ __forceinline__ void mma_bf16(float* c, const unsigned* a, const unsigned* b) {
    asm volatile("mma.sync.aligned.m16n8k16.row.col.f32.bf16.bf16.f32 "
        "{%0,%1,%2,%3},{%4,%5,%6,%7},{%8,%9},{%0,%1,%2,%3};"
        : "+f"(c[0]),"+f"(c[1]),"+f"(c[2]),"+f"(c[3])
        : "r"(a[0]),"r"(a[1]),"r"(a[2]),"r"(a[3]),"r"(b[0]),"r"(b[1]));
}
__device__ __forceinline__ void bsplit(float v, __nv_bfloat16* ph, __nv_bfloat16* pl) {
    __nv_bfloat16 h = __float2bfloat16(v);
    *ph = h;
    *pl = __float2bfloat16(v - __bfloat162float(h));
}
// buffer selector: 0=F0, 1=FC0, 2=F1, 3=FC1
__device__ __forceinline__ void selbuf(int sel, const __nv_bfloat16*& h, const __nv_bfloat16*& l,
                                       __nv_bfloat16*& oh, __nv_bfloat16*& ol) {
    if (sel == 0)      { oh = g_F0h;  ol = g_F0l; }
    else if (sel == 1) { oh = g_FC0h; ol = g_FC0l; }
    else if (sel == 2) { oh = g_F1h;  ol = g_F1l; }
    else               { oh = g_FC1h; ol = g_FC1l; }
    h = oh; l = ol;
}

// ---------------- setup kernels ----------------
__global__ void transpose_kernel(const float* __restrict__ G) {
    __shared__ float t[32][33];
    int x = blockIdx.x*32 + threadIdx.x, y = blockIdx.y*32 + threadIdx.y;
    t[threadIdx.y][threadIdx.x] = G[y*N_ + x];
    __syncthreads();
    int x2 = blockIdx.y*32 + threadIdx.x, y2 = blockIdx.x*32 + threadIdx.y;
    g_A2[y2*N_ + x2] = t[threadIdx.x][threadIdx.y];
}

__global__ void __launch_bounds__(256) g2_kernel() {
    __shared__ float As[8][128], Bs[8][128];
    int tid = threadIdx.x;
    int i0 = blockIdx.y*128, j0 = blockIdx.x*128;
    int ty = tid>>4, tx = tid&15, rl = ty*4, cl = tx*4;
    int ar = tid>>1, ac = (tid&1)*4;
    int bk = tid>>5, bj = (tid&31)*4;
    float acc[8][8];
    #pragma unroll
    for (int i=0;i<8;i++) {
        #pragma unroll
        for (int j=0;j<8;j++) acc[i][j]=0.f;
    }
    for (int k0=0;k0<N_;k0+=8) {
        float4 av = make_float4(0,0,0,0);
        if (i0+ar < N_) av = *(const float4*)&g_A2[(long)(i0+ar)*N_ + k0+ac];
        As[ac+0][ar]=av.x; As[ac+1][ar]=av.y; As[ac+2][ar]=av.z; As[ac+3][ar]=av.w;
        float4 bv = make_float4(0,0,0,0);
        if (j0+bj < N_) bv = *(const float4*)&g_A2[(long)(k0+bk)*N_ + j0+bj];
        *(float4*)&Bs[bk][bj] = bv;
        __syncthreads();
        #pragma unroll
        for (int kk=0;kk<8;kk++) {
            float a[8], b[8];
            *(float4*)a     = *(const float4*)&As[kk][rl];
            *(float4*)(a+4) = *(const float4*)&As[kk][rl+64];
            *(float4*)b     = *(const float4*)&Bs[kk][cl];
            *(float4*)(b+4) = *(const float4*)&Bs[kk][cl+64];
            #pragma unroll
            for (int i=0;i<8;i++) {
                #pragma unroll
                for (int j=0;j<8;j++) acc[i][j] += a[i]*b[j];
            }
        }
        __syncthreads();
    }
    #pragma unroll
    for (int i=0;i<8;i++) {
        int r = i0 + (i<4 ? rl+i : 64+rl+i-4);
        if (r >= N_) continue;
        #pragma unroll
        for (int j=0;j<8;j++) {
            int c = j0 + (j<4 ? cl+j : 64+cl+j-4);
            if (c >= N_) continue;
            g_A2[(long)(N_+r)*N_ + c] = 2.f*acc[i][j] - (r==c ? 1.f : 0.f);
        }
    }
}

__global__ void split_a2() {
    int i = blockIdx.x*256 + threadIdx.x;
    if (i >= MPAD*800) return;
    float v = (i < 1600*800) ? g_A2[i] : 0.f;
    bsplit(v, &g_A2h[i], &g_A2l[i]);
}

__global__ void fold_split(const float* __restrict__ W, int isGate, int widx,
                           int P, int O, int KT) {
    int idx = blockIdx.x*256 + threadIdx.x;
    if (idx >= KT*O) return;
    int row = idx / O, o = idx % O;
    float v = 0.f;
    if (row < 3*P) {
        int k = row / P, p = row % P;
        if (k == 0) v = W[idx] + KAPPA_*(W[(P+p)*O + o] + W[(2*P+p)*O + o]);
        else        v = (1.f - KAPPA_)*W[idx];
    }
    if (isGate) bsplit(v, &g_WGh[widx][idx], &g_WGl[widx][idx]);
    else        bsplit(v, &g_WCh[widx][idx], &g_WCl[widx][idx]);
}

__global__ void mlp_kernel(const float* __restrict__ Tin,
                           const float* __restrict__ W1, const float* __restrict__ b1,
                           const float* __restrict__ W2, const float* __restrict__ b2,
                           int dsel) {
    float* out = dsel ? g_EMBY : g_EMBX;
    int r = blockIdx.x, tid = threadIdx.x;
    __shared__ float tin[60];
    __shared__ float hid[10];
    if (tid < 60) tin[tid] = Tin[(long)r*60 + tid];
    __syncthreads();
    if (tid < 10) {
        float s = b1[tid];
        for (int i = 0; i < 60; i++) s += tin[i]*W1[i*10 + tid];
        hid[tid] = s;
    }
    __syncthreads();
    for (int o = tid; o < N_*TC_H; o += 256) {
        float s = b2[o];
        #pragma unroll
        for (int j = 0; j < 10; j++) s += hid[j]*W2[j*(N_*TC_H) + o];
        out[(long)r*(N_*TC_H) + o] = s;
    }
}

__global__ void zero_state() {
    long i = (long)blockIdx.x*256 + threadIdx.x;
    __nv_bfloat16 z = __float2bfloat16(0.f);
    if (i < NB*H_) { g_H0[i] = 0.f; g_H1[i] = 0.f; }
    if (i < NB*CIN_) g_GO[i] = 0.f;
    if (i < (long)NB*CF0) { g_F0h[i]=z; g_F0l[i]=z; g_FC0h[i]=z; g_FC0l[i]=z; }
    if (i < (long)NB*CF1) { g_F1h[i]=z; g_F1l[i]=z; g_FC1h[i]=z; g_FC1l[i]=z; }
}

// ---------------- tiny per-step builders ----------------
// writes cols 0-3 of F0 and FC0: [x|emb] (encoder) or [GO|emb] (decoder)
__global__ void build_x0(const float* __restrict__ xs, int t, int isDec) {
    int idx = blockIdx.x*256 + threadIdx.x;
    if (idx >= NB*4) return;
    int c = idx & 3, row = idx >> 2;
    int b = row % B_, n = row / B_;
    float v;
    if (c < 2) v = isDec ? g_GO[row*2 + c]
                         : xs[((long)(b*T_ + t)*N_ + n)*CIN_ + c];
    else       v = isDec ? g_EMBY[(long)(b*HOR_ + t)*(N_*TC_H) + n*TC_H + (c-2)]
                         : g_EMBX[(long)(b*T_ + t)*(N_*TC_H) + n*TC_H + (c-2)];
    long a = (long)row*CF0 + c;
    __nv_bfloat16 h, l; bsplit(v, &h, &l);
    g_F0h[a]=h; g_F0l[a]=l; g_FC0h[a]=h; g_FC0l[a]=l;
}

// copy Y1/Y2 x-prefixes (cols 68-71,136-139) from F0 into FC0
__global__ void copy_fcY() {
    int idx = blockIdx.x*256 + threadIdx.x;
    if (idx >= NB*8) return;
    int j = idx & 7, row = idx >> 3;
    int c = (j < 4) ? (68 + j) : (136 + (j-4));
    long a = (long)row*CF0 + c;
    g_FC0h[a] = g_F0h[a]; g_FC0l[a] = g_F0l[a];
}

// ---------------- tensor-core graph propagation (cp.async, 128x128 tile) ------
__global__ void __launch_bounds__(256) prop_tc(int sel, int CF, int src_off,
                                               int d1, int d2, int Psub) {
    const __nv_bfloat16 *Fh, *Fl; __nv_bfloat16 *Oh, *Ol;
    selbuf(sel, Fh, Fl, Oh, Ol);
    __shared__ __align__(16) __nv_bfloat16 Ah[2][128][24], Al[2][128][24];
    __shared__ __align__(16) __nv_bfloat16 Bh[2][16][136], Bl[2][16][136];
    int tid = threadIdx.x, lane = tid & 31, warp = tid >> 5;
    int m0 = blockIdx.y*128, n0 = blockIdx.x*128;
    int wm = warp >> 2, wn = warp & 3;
    long rowStride = (long)B_*CF;

    float acc[4][4][4];
    #pragma unroll
    for (int i=0;i<4;i++)
        #pragma unroll
        for (int j=0;j<4;j++)
            #pragma unroll
            for (int e=0;e<4;e++) acc[i][j][e]=0.f;

    int aRow = tid >> 1, aSeg = (tid & 1)*8;
    long aBase = (long)(m0 + aRow)*800 + aSeg;
    int kr0 = tid >> 5,        cc0 = (tid & 31)*4;
    int kr1 = (tid+256) >> 5,  cc1 = (tid & 31)*4;
    int j0g = n0 + cc0, j1g = n0 + cc1;
    int bo0 = j0g/Psub, co0 = j0g - bo0*Psub;
    int bo1 = j1g/Psub, co1 = j1g - bo1*Psub;
    long bOff0 = (long)bo0*CF + src_off + co0;
    long bOff1 = (long)bo1*CF + src_off + co1;

    auto issue = [&](int k0, int s) {
        cp16(&Ah[s][aRow][aSeg], g_A2h + aBase + k0);
        cp16(&Al[s][aRow][aSeg], g_A2l + aBase + k0);
        long a0 = (long)(k0+kr0)*rowStride + bOff0;
        long a1 = (long)(k0+kr1)*rowStride + bOff1;
        cp8(&Bh[s][kr0][cc0], Fh + a0);
        cp8(&Bl[s][kr0][cc0], Fl + a0);
        cp8(&Bh[s][kr1][cc1], Fh + a1);
        cp8(&Bl[s][kr1][cc1], Fl + a1);
        cp_commit();
    };

    int grp = lane >> 3, rr = lane & 7;
    int arow = ((grp & 1) ? 8 : 0) + rr;
    int acol = (grp & 2) ? 8 : 0;
    int brow = lane & 15;

    issue(0, 0);
    for (int c = 0; c < 50; c++) {
        if (c < 49) { issue((c+1)*16, (c+1)&1); asm volatile("cp.async.wait_group 1;"); }
        else        { asm volatile("cp.async.wait_group 0;"); }
        __syncthreads();
        int s = c & 1;
        unsigned fah[4][4], fal[4][4], fbh[4][2], fbl[4][2];
        #pragma unroll
        for (int mi=0; mi<4; mi++) {
            ldsm_x4(fah[mi], su(&Ah[s][wm*64 + mi*16 + arow][acol]));
            ldsm_x4(fal[mi], su(&Al[s][wm*64 + mi*16 + arow][acol]));
        }
        #pragma unroll
        for (int ni=0; ni<4; ni++) {
            ldsm_x2t(fbh[ni], su(&Bh[s][brow][wn*32 + ni*8]));
            ldsm_x2t(fbl[ni], su(&Bl[s][brow][wn*32 + ni*8]));
        }
        #pragma unroll
        for (int mi=0; mi<4; mi++)
            #pragma unroll
            for (int ni=0; ni<4; ni++) {
                mma_bf16(acc[mi][ni], fah[mi], fbh[ni]);
                mma_bf16(acc[mi][ni], fah[mi], fbl[ni]);
                mma_bf16(acc[mi][ni], fal[mi], fbh[ni]);
            }
        __syncthreads();
    }

    #pragma unroll
    for (int mi=0; mi<4; mi++)
        #pragma unroll
        for (int ni=0; ni<4; ni++) {
            int rb = m0 + wm*64 + mi*16 + (lane >> 2);
            int cb = n0 + wn*32 + ni*8 + 2*(lane & 3);
            int bo = cb / Psub, co = cb - bo*Psub;
            #pragma unroll
            for (int hh=0; hh<2; hh++) {
                int gr = rb + hh*8;
                if (gr >= 1600) continue;
                int gm  = (gr < 800) ? gr : gr - 800;
                int off = (gr < 800) ? d1 : d2;
                long a = (long)gm*rowStride + (long)bo*CF + off + co;
                float v0 = acc[mi][ni][2*hh], v1 = acc[mi][ni][2*hh+1];
                __nv_bfloat16 h0 = __float2bfloat16(v0);
                __nv_bfloat16 h1 = __float2bfloat16(v1);
                __nv_bfloat16 l0 = __float2bfloat16(v0 - __bfloat162float(h0));
                __nv_bfloat16 l1 = __float2bfloat16(v1 - __bfloat162float(h1));
                *(__nv_bfloat162*)&Oh[a] = __halves2bfloat162(h0, h1);
                *(__nv_bfloat162*)&Ol[a] = __halves2bfloat162(l0, l1);
            }
        }
}

// ---------------- tensor-core projection + fully-fused GRU epilogues ----------
// MODE 0 (gate, NO=128):  UR = sigmoid(.); for r-cols also write rh splits to FC buf
// MODE 1 (cand, NO=64):   h' = (1-u)h + u*tanh(.); write h' fp32 + splits to F bufs
// srcMode: 0=F0, 1=FC0, 2=F1, 3=FC1, 4=parity F1/FC1 on (k>>6)&1
template<int NO, int MODE>
__global__ void __launch_bounds__(256) proj_tc(int srcMode, int CF, int KT, int wsel,
                                               const float* __restrict__ bias, int hsel) {
    const __nv_bfloat16* Wh = (MODE==0) ? g_WGh[wsel] : g_WCh[wsel];
    const __nv_bfloat16* Wl = (MODE==0) ? g_WGl[wsel] : g_WCl[wsel];
    constexpr int WN = NO/32;
    constexpr int WM = 8/WN;
    constexpr int MT = (128/WM)/16;
    __shared__ __align__(16) __nv_bfloat16 Ah[2][128][24], Al[2][128][24];
    __shared__ __align__(16) __nv_bfloat16 Bh[2][16][NO+8], Bl[2][16][NO+8];
    int tid = threadIdx.x, lane = tid & 31, warp = tid >> 5;
    long row0 = (long)blockIdx.x*128;
    int wm = warp / WN, wn = warp % WN;
    float acc[MT][4][4];
    #pragma unroll
    for (int i=0;i<MT;i++)
        #pragma unroll
        for (int j=0;j<4;j++)
            #pragma unroll
            for (int e=0;e<4;e++) acc[i][j][e]=0.f;

    int aRow = tid >> 1, aSeg = (tid & 1)*8;
    long aBase = (row0 + aRow)*CF + aSeg;

    auto issue = [&](int k0, int s) {
        const __nv_bfloat16 *Sh, *Sl;
        if (srcMode == 0)       { Sh = g_F0h;  Sl = g_F0l; }
        else if (srcMode == 1)  { Sh = g_FC0h; Sl = g_FC0l; }
        else if (srcMode == 2)  { Sh = g_F1h;  Sl = g_F1l; }
        else if (srcMode == 3)  { Sh = g_FC1h; Sl = g_FC1l; }
        else if ((k0 >> 6) & 1) { Sh = g_FC1h; Sl = g_FC1l; }
        else                    { Sh = g_F1h;  Sl = g_F1l; }
        cp16(&Ah[s][aRow][aSeg], Sh + aBase + k0);
        cp16(&Al[s][aRow][aSeg], Sl + aBase + k0);
        if (NO == 128) {
            int wr = tid >> 4, wc = (tid & 15)*8;
            long a = (long)(k0+wr)*NO + wc;
            cp16(&Bh[s][wr][wc], Wh + a);
            cp16(&Bl[s][wr][wc], Wl + a);
        } else if (tid < 128) {
            int wr = tid >> 3, wc = (tid & 7)*8;
            long a = (long)(k0+wr)*NO + wc;
            cp16(&Bh[s][wr][wc], Wh + a);
            cp16(&Bl[s][wr][wc], Wl + a);
        }
        cp_commit();
    };

    int grp = lane >> 3, rr = lane & 7;
    int arow = ((grp & 1) ? 8 : 0) + rr;
    int acol = (grp & 2) ? 8 : 0;
    int brow = lane & 15;

    int NC = KT / 16;
    issue(0, 0);
    for (int c = 0; c < NC; c++) {
        if (c < NC-1) { issue((c+1)*16, (c+1)&1); asm volatile("cp.async.wait_group 1;"); }
        else          { asm volatile("cp.async.wait_group 0;"); }
        __syncthreads();
        int s = c & 1;
        unsigned fah[MT][4], fal[MT][4], fbh[4][2], fbl[4][2];
        #pragma unroll
        for (int mi=0; mi<MT; mi++) {
            ldsm_x4(fah[mi], su(&Ah[s][wm*(MT*16) + mi*16 + arow][acol]));
            ldsm_x4(fal[mi], su(&Al[s][wm*(MT*16) + mi*16 + arow][acol]));
        }
        #pragma unroll
        for (int ni=0; ni<4; ni++) {
            int cc = wn*32 + ni*8;
            ldsm_x2t(fbh[ni], su(&Bh[s][brow][cc]));
            ldsm_x2t(fbl[ni], su(&Bl[s][brow][cc]));
        }
        #pragma unroll
        for (int mi=0; mi<MT; mi++)
            #pragma unroll
            for (int ni=0; ni<4; ni++) {
                mma_bf16(acc[mi][ni], fah[mi], fbh[ni]);
                mma_bf16(acc[mi][ni], fah[mi], fbl[ni]);
                mma_bf16(acc[mi][ni], fal[mi], fbh[ni]);
            }
        __syncthreads();
    }

    float* Hb = hsel ? g_H1 : g_H0;
    #pragma unroll
    for (int mi=0; mi<MT; mi++)
        #pragma unroll
        for (int ni=0; ni<4; ni++) {
            long rb = row0 + wm*(MT*16) + mi*16 + (lane >> 2);
            int  cb = wn*32 + ni*8 + 2*(lane & 3);
            #pragma unroll
            for (int e=0; e<4; e++) {
                long row = rb + ((e >= 2) ? 8 : 0);
                int  c   = cb + (e & 1);
                float v = acc[mi][ni][e] + bias[c];
                if (MODE == 0) {
                    float sg = 1.f/(1.f + expf(-v));
                    g_UR[row*128 + c] = sg;
                    if (c >= 64) {        // r-column: write r*h splits into FC buffer
                        int cc2 = c - 64;
                        float rh = sg * Hb[row*64 + cc2];
                        if (hsel == 0) {
                            long a = row*(long)CF0 + 4 + cc2;
                            bsplit(rh, &g_FC0h[a], &g_FC0l[a]);
                        } else {
                            long a = row*(long)CF1 + 64 + cc2;
                            bsplit(rh, &g_FC1h[a], &g_FC1l[a]);
                        }
                    }
                } else {
                    float cv = tanhf(v);
                    float u  = g_UR[row*128 + c];
                    float h  = Hb[row*64 + c];
                    float hn = (1.f - u)*h + u*cv;
                    Hb[row*64 + c] = hn;
                    if (hsel == 0) {      // h0: feeds cell1 gate now + cell0 next step
                        long a1 = row*(long)CF1 + c;
                        bsplit(hn, &g_F1h[a1], &g_F1l[a1]);
                        long a0 = row*(long)CF0 + 4 + c;
                        bsplit(hn, &g_F0h[a0], &g_F0l[a0]);
                    } else {              // h1: feeds cell1 gate next step
                        long a1 = row*(long)CF1 + 64 + c;
                        bsplit(hn, &g_F1h[a1], &g_F1l[a1]);
                    }
                }
            }
        }
}

// ---------------- decoder memory attention + output projection ----------------
__global__ void query_kernel(const float* __restrict__ Wa) {
    int b = blockIdx.x, tid = threadIdx.x;
    float p[8];
    #pragma unroll
    for (int d = 0; d < 8; d++) p[d] = 0.f;
    for (int idx = tid; idx < N_*H_; idx += 256) {
        int n = idx >> 6, j = idx & 63;
        float v = g_H1[(long)(n*B_ + b)*64 + j];
        const float* w = Wa + (long)idx*8;
        #pragma unroll
        for (int d = 0; d < 8; d++) p[d] += v*w[d];
    }
    #pragma unroll
    for (int d = 0; d < 8; d++)
        for (int off = 16; off > 0; off >>= 1) p[d] += __shfl_down_sync(0xffffffffu, p[d], off);
    __shared__ float sm[8][8];
    int w = tid >> 5, l = tid & 31;
    if (l == 0) { for (int d = 0; d < 8; d++) sm[w][d] = p[d]; }
    __syncthreads();
    if (tid < 8) {
        float s = 0.f;
        for (int ww = 0; ww < 8; ww++) s += sm[ww][tid];
        g_Q[b*8 + tid] = s;
    }
}

__global__ void attm_kernel(const float* __restrict__ mem, const float* __restrict__ fcw) {
    int b = blockIdx.x, tid = threadIdx.x;
    __shared__ float am[8];
    if (tid == 0) {
        float q[8];
        for (int d = 0; d < 8; d++) q[d] = g_Q[b*8 + d];
        float s[4]; float mx = -1e30f;
        for (int m = 0; m < 4; m++) {
            float a = 0.f;
            for (int d = 0; d < 8; d++) a += q[d]*mem[m*8 + d];
            s[m] = a; mx = fmaxf(mx, a);
        }
        float den = 0.f;
        for (int m = 0; m < 4; m++) { s[m] = expf(s[m]-mx); den += s[m]; }
        for (int d = 0; d < 8; d++) {
            float a = 0.f;
            for (int m = 0; m < 4; m++) a += (s[m]/den)*mem[m*8 + d];
            am[d] = a;
        }
    }
    __syncthreads();
    for (int i = tid; i < N_*8; i += 256) {
        float s = 0.f;
        #pragma unroll
        for (int d = 0; d < 8; d++) s += am[d]*fcw[(long)d*(N_*8) + i];
        g_ATTM[(long)b*(N_*8) + i] = s;
    }
}

__global__ void out_kernel(const float* __restrict__ pW, const float* __restrict__ pb,
                           float* __restrict__ outp, int s) {
    int row = blockIdx.x*256 + threadIdx.x;
    if (row >= NB) return;
    int b = row % B_, n = row / B_;
    float a0 = pb[0], a1 = pb[1];
    const float* h = g_H1 + (long)row*64;
    #pragma unroll
    for (int j = 0; j < 64; j++) { float v = h[j]; a0 += v*pW[j*2]; a1 += v*pW[j*2+1]; }
    const float* at = g_ATTM + (long)b*(N_*8) + n*8;
    #pragma unroll
    for (int d = 0; d < 8; d++) { float v = at[d]; a0 += v*pW[(64+d)*2]; a1 += v*pW[(64+d)*2+1]; }
    a0 = fmaxf(a0, 0.f); a1 = fmaxf(a1, 0.f);
    g_GO[row*2] = a0; g_GO[row*2+1] = a1;
    long o = ((long)(b*HOR_ + s)*N_ + n)*CIN_;
    outp[o] = a0; outp[o+1] = a1;
}

// ---------------- orchestration ----------------
extern "C" void kernel_launch(void* const* d_in, const int* in_sizes, int n_in,
                              void* d_out, int out_size) {
    (void)in_sizes; (void)n_in; (void)out_size;
    const float* x_seq = (const float*)d_in[0];
    const float* t_x   = (const float*)d_in[1];
    const float* t_y   = (const float*)d_in[2];
    const float* G     = (const float*)d_in[3];
    const float* eWg0  = (const float*)d_in[4];  const float* ebg0 = (const float*)d_in[5];
    const float* eWc0  = (const float*)d_in[6];  const float* ebc0 = (const float*)d_in[7];
    const float* eWg1  = (const float*)d_in[8];  const float* ebg1 = (const float*)d_in[9];
    const float* eWc1  = (const float*)d_in[10]; const float* ebc1 = (const float*)d_in[11];
    const float* dWg0  = (const float*)d_in[12]; const float* dbg0 = (const float*)d_in[13];
    const float* dWc0  = (const float*)d_in[14]; const float* dbc0 = (const float*)d_in[15];
    const float* dWg1  = (const float*)d_in[16]; const float* dbg1 = (const float*)d_in[17];
    const float* dWc1  = (const float*)d_in[18]; const float* dbc1 = (const float*)d_in[19];
    const float* mW1   = (const float*)d_in[20]; const float* mb1  = (const float*)d_in[21];
    const float* mW2   = (const float*)d_in[22]; const float* mb2  = (const float*)d_in[23];
    const float* mem   = (const float*)d_in[24];
    const float* Wa    = (const float*)d_in[25];
    const float* fcw   = (const float*)d_in[26];
    const float* projW = (const float*)d_in[27];
    const float* projb = (const float*)d_in[28];
    float* outp = (float*)d_out;

    transpose_kernel<<<dim3(25,25), dim3(32,32)>>>(G);
    g2_kernel<<<dim3(7,7), 256>>>();
    split_a2<<<(MPAD*800+255)/256, 256>>>();

    auto fold = [](const float* W, int isGate, int widx, int P, int O) {
        int KT = ((3*P + 15)/16)*16;
        fold_split<<<(KT*O+255)/256, 256>>>(W, isGate, widx, P, O, KT);
    };
    fold(eWg0,1,0,68,128);  fold(eWc0,0,0,68,64);
    fold(eWg1,1,1,128,128); fold(eWc1,0,1,128,64);
    fold(dWg0,1,2,68,128);  fold(dWc0,0,2,68,64);
    fold(dWg1,1,3,128,128); fold(dWc1,0,3,128,64);

    mlp_kernel<<<B_*T_,   256>>>(t_x, mW1, mb1, mW2, mb2, 0);
    mlp_kernel<<<B_*HOR_, 256>>>(t_y, mW1, mb1, mW2, mb2, 1);
    zero_state<<<((long)NB*CF1 + 255)/256, 256>>>();

    auto step = [&](int wsel0, int wsel1,
                    const float* bg0, const float* bc0,
                    const float* bg1, const float* bc1) {
        // cell0
        prop_tc<<<dim3(34,13), 256>>>(0, CF0, 0, 68, 136, 68);
        proj_tc<128,0><<<NB/128, 256>>>(0, CF0, 208, wsel0, bg0, 0);
        copy_fcY<<<(NB*8+255)/256, 256>>>();
        prop_tc<<<dim3(32,13), 256>>>(1, CF0, 4, 72, 140, 64);
        proj_tc<64,1><<<NB/128, 256>>>(1, CF0, 208, wsel0, bc0, 0);
        // cell1
        prop_tc<<<dim3(64,13), 256>>>(2, CF1, 0, 128, 256, 128);
        proj_tc<128,0><<<NB/128, 256>>>(2, CF1, 384, wsel1, bg1, 1);
        prop_tc<<<dim3(32,13), 256>>>(3, CF1, 64, 192, 320, 64);
        proj_tc<64,1><<<NB/128, 256>>>(4, CF1, 384, wsel1, bc1, 1);
    };

    // encoder
    for (int t = 0; t < T_; t++) {
        build_x0<<<(NB*4+255)/256, 256>>>(x_seq, t, 0);
        step(0, 1, ebg0, ebc0, ebg1, ebc1);
    }
    // decoder
    for (int s = 0; s < HOR_; s++) {
        build_x0<<<(NB*4+255)/256, 256>>>(x_seq, s, 1);
        step(2, 3, dbg0, dbc0, dbg1, dbc1);
        query_kernel<<<B_, 256>>>(Wa);
        attm_kernel<<<B_, 256>>>(mem, fcw);
        out_kernel<<<NB/256, 256>>>(projW, projb, outp, s);
    }
}

// round 10
// speedup vs baseline: 1.1042x; 1.1042x over previous
#include <cuda_runtime.h>
#include <cuda_bf16.h>
#include <stdint.h>
#include <math.h>

#define B_    64
#define T_    12
#define N_    800
#define CIN_  2
#define H_    64
#define HOR_  12
#define TC_H  2
#define KAPPA_ 0.05f
#define NB    (N_*B_)
#define CF0   208
#define CF1   384
#define MPAD  1664

// ---------------- device scratch ----------------
__device__ float g_A2[1600*800];
__device__ __align__(16) __nv_bfloat16 g_A2h[MPAD*800];
__device__ __align__(16) __nv_bfloat16 g_A2l[MPAD*800];
__device__ float g_EMBX[B_*T_*N_*TC_H];
__device__ float g_EMBY[B_*HOR_*N_*TC_H];
__device__ float g_H0[NB*H_];
__device__ float g_H1[NB*H_];
__device__ float g_UR[NB*128];
__device__ float g_GO[NB*CIN_];
__device__ float g_Q [B_*8];
__device__ float g_ATTM[B_*N_*8];
__device__ __align__(16) __nv_bfloat16 g_Fh [NB*384];
__device__ __align__(16) __nv_bfloat16 g_Fl [NB*384];
__device__ __align__(16) __nv_bfloat16 g_FCh[NB*384];
__device__ __align__(16) __nv_bfloat16 g_FCl[NB*384];
__device__ __align__(16) __nv_bfloat16 g_WGh[4][384*128];
__device__ __align__(16) __nv_bfloat16 g_WGl[4][384*128];
__device__ __align__(16) __nv_bfloat16 g_WCh[4][384*64];
__device__ __align__(16) __nv_bfloat16 g_WCl[4][384*64];

// ---------------- helpers ----------------
__device__ __forceinline__ unsigned su(void* p) {
    return (unsigned)__cvta_generic_to_shared(p);
}
__device__ __forceinline__ void cp16(void* dst, const void* src) {
    asm volatile("cp.async.ca.shared.global [%0],[%1],16;" :: "r"(su(dst)), "l"(src));
}
__device__ __forceinline__ void cp8(void* dst, const void* src) {
    asm volatile("cp.async.ca.shared.global [%0],[%1],8;" :: "r"(su(dst)), "l"(src));
}
__device__ __forceinline__ void cp_commit() {
    asm volatile("cp.async.commit_group;");
}
__device__ __forceinline__ void ldsm_x4(unsigned* r, unsigned addr) {
    asm volatile("ldmatrix.sync.aligned.m8n8.x4.shared.b16 {%0,%1,%2,%3},[%4];"
        : "=r"(r[0]),"=r"(r[1]),"=r"(r[2]),"=r"(r[3]) : "r"(addr));
}
__device__ __forceinline__ void ldsm_x2t(unsigned* r, unsigned addr) {
    asm volatile("ldmatrix.sync.aligned.m8n8.x2.trans.shared.b16 {%0,%1},[%2];"
        : "=r"(r[0]),"=r"(r[1]) : "r"(addr));
}
__device__ __forceinline__ void mma_bf16(float* c, const unsigned* a, const unsigned* b) {
    asm volatile("mma.sync.aligned.m16n8k16.row.col.f32.bf16.bf16.f32 "
        "{%0,%1,%2,%3},{%4,%5,%6,%7},{%8,%9},{%0,%1,%2,%3};"
        : "+f"(c[0]),"+f"(c[1]),"+f"(c[2]),"+f"(c[3])
        : "r"(a[0]),"r"(a[1]),"r"(a[2]),"r"(a[3]),"r"(b[0]),"r"(b[1]));
}
__device__ __forceinline__ void bsplit(float v, __nv_bfloat16* ph, __nv_bfloat16* pl) {
    __nv_bfloat16 h = __float2bfloat16(v);
    *ph = h;
    *pl = __float2bfloat16(v - __bfloat162float(h));
}

// ---------------- setup kernels ----------------
__global__ void transpose_kernel(const float* __restrict__ G) {
    __shared__ float t[32][33];
    int x = blockIdx.x*32 + threadIdx.x, y = blockIdx.y*32 + threadIdx.y;
    t[threadIdx.y][threadIdx.x] = G[y*N_ + x];
    __syncthreads();
    int x2 = blockIdx.y*32 + threadIdx.x, y2 = blockIdx.x*32 + threadIdx.y;
    g_A2[y2*N_ + x2] = t[threadIdx.x][threadIdx.y];
}

__global__ void __launch_bounds__(256) g2_kernel() {
    __shared__ float As[8][128], Bs[8][128];
    int tid = threadIdx.x;
    int i0 = blockIdx.y*128, j0 = blockIdx.x*128;
    int ty = tid>>4, tx = tid&15, rl = ty*4, cl = tx*4;
    int ar = tid>>1, ac = (tid&1)*4;
    int bk = tid>>5, bj = (tid&31)*4;
    float acc[8][8];
    #pragma unroll
    for (int i=0;i<8;i++) {
        #pragma unroll
        for (int j=0;j<8;j++) acc[i][j]=0.f;
    }
    for (int k0=0;k0<N_;k0+=8) {
        float4 av = make_float4(0,0,0,0);
        if (i0+ar < N_) av = *(const float4*)&g_A2[(long)(i0+ar)*N_ + k0+ac];
        As[ac+0][ar]=av.x; As[ac+1][ar]=av.y; As[ac+2][ar]=av.z; As[ac+3][ar]=av.w;
        float4 bv = make_float4(0,0,0,0);
        if (j0+bj < N_) bv = *(const float4*)&g_A2[(long)(k0+bk)*N_ + j0+bj];
        *(float4*)&Bs[bk][bj] = bv;
        __syncthreads();
        #pragma unroll
        for (int kk=0;kk<8;kk++) {
            float a[8], b[8];
            *(float4*)a     = *(const float4*)&As[kk][rl];
            *(float4*)(a+4) = *(const float4*)&As[kk][rl+64];
            *(float4*)b     = *(const float4*)&Bs[kk][cl];
            *(float4*)(b+4) = *(const float4*)&Bs[kk][cl+64];
            #pragma unroll
            for (int i=0;i<8;i++) {
                #pragma unroll
                for (int j=0;j<8;j++) acc[i][j] += a[i]*b[j];
            }
        }
        __syncthreads();
    }
    #pragma unroll
    for (int i=0;i<8;i++) {
        int r = i0 + (i<4 ? rl+i : 64+rl+i-4);
        if (r >= N_) continue;
        #pragma unroll
        for (int j=0;j<8;j++) {
            int c = j0 + (j<4 ? cl+j : 64+cl+j-4);
            if (c >= N_) continue;
            g_A2[(long)(N_+r)*N_ + c] = 2.f*acc[i][j] - (r==c ? 1.f : 0.f);
        }
    }
}

__global__ void split_a2() {
    int i = blockIdx.x*256 + threadIdx.x;
    if (i >= MPAD*800) return;
    float v = (i < 1600*800) ? g_A2[i] : 0.f;
    bsplit(v, &g_A2h[i], &g_A2l[i]);
}

__global__ void fold_split(const float* __restrict__ W, int isGate, int widx,
                           int P, int O, int KT) {
    int idx = blockIdx.x*256 + threadIdx.x;
    if (idx >= KT*O) return;
    int row = idx / O, o = idx % O;
    float v = 0.f;
    if (row < 3*P) {
        int k = row / P, p = row % P;
        if (k == 0) v = W[idx] + KAPPA_*(W[(P+p)*O + o] + W[(2*P+p)*O + o]);
        else        v = (1.f - KAPPA_)*W[idx];
    }
    if (isGate) bsplit(v, &g_WGh[widx][idx], &g_WGl[widx][idx]);
    else        bsplit(v, &g_WCh[widx][idx], &g_WCl[widx][idx]);
}

__global__ void mlp_kernel(const float* __restrict__ Tin,
                           const float* __restrict__ W1, const float* __restrict__ b1,
                           const float* __restrict__ W2, const float* __restrict__ b2,
                           int dsel) {
    float* out = dsel ? g_EMBY : g_EMBX;
    int r = blockIdx.x, tid = threadIdx.x;
    __shared__ float tin[60];
    __shared__ float hid[10];
    if (tid < 60) tin[tid] = Tin[(long)r*60 + tid];
    __syncthreads();
    if (tid < 10) {
        float s = b1[tid];
        for (int i = 0; i < 60; i++) s += tin[i]*W1[i*10 + tid];
        hid[tid] = s;
    }
    __syncthreads();
    for (int o = tid; o < N_*TC_H; o += 256) {
        float s = b2[o];
        #pragma unroll
        for (int j = 0; j < 10; j++) s += hid[j]*W2[j*(N_*TC_H) + o];
        out[(long)r*(N_*TC_H) + o] = s;
    }
}

__global__ void zero_state() {
    int i = blockIdx.x*256 + threadIdx.x;
    if (i < NB*H_) { g_H0[i] = 0.f; g_H1[i] = 0.f; }
    if (i < NB*CIN_) g_GO[i] = 0.f;
    if (i < NB*4) {
        int row = i >> 2, c = 204 + (i & 3);
        long a = (long)row*CF0 + c;
        __nv_bfloat16 z = __float2bfloat16(0.f);
        g_Fh[a] = z; g_Fl[a] = z; g_FCh[a] = z; g_FCl[a] = z;
    }
}

// ---------------- feature builders (coalesced, dedicated kernels) -------------
__global__ void build_xh0(const float* __restrict__ xs, int t, int isDec) {
    int idx = blockIdx.x*256 + threadIdx.x;
    if (idx >= NB*68) return;
    int c = idx % 68, row = idx / 68;
    int b = row % B_, n = row / B_;
    float v;
    if (isDec) {
        if (c < 2)      v = g_GO[row*2 + c];
        else if (c < 4) v = g_EMBY[(long)(b*HOR_ + t)*(N_*TC_H) + n*TC_H + (c-2)];
        else            v = g_H0[(long)row*64 + (c-4)];
    } else {
        if (c < 2)      v = xs[((long)(b*T_ + t)*N_ + n)*CIN_ + c];
        else if (c < 4) v = g_EMBX[(long)(b*T_ + t)*(N_*TC_H) + n*TC_H + (c-2)];
        else            v = g_H0[(long)row*64 + (c-4)];
    }
    long a = (long)row*CF0 + c;
    bsplit(v, &g_Fh[a], &g_Fl[a]);
}

__global__ void build_xh1() {
    int idx = blockIdx.x*256 + threadIdx.x;
    if (idx >= NB*128) return;
    int c = idx % 128, row = idx / 128;
    float v = (c < 64) ? g_H0[(long)row*64 + c] : g_H1[(long)row*64 + (c-64)];
    long a = (long)row*CF1 + c;
    bsplit(v, &g_Fh[a], &g_Fl[a]);
}

__global__ void build_fc0() {
    int idx = blockIdx.x*256 + threadIdx.x;
    if (idx >= NB*76) return;
    int j = idx % 76, row = idx / 76;
    long base = (long)row*CF0;
    if (j < 4) {
        g_FCh[base+j] = g_Fh[base+j]; g_FCl[base+j] = g_Fl[base+j];
    } else if (j < 68) {
        int c = j - 4;
        float v = g_UR[(long)row*128 + 64 + c] * g_H0[(long)row*64 + c];
        bsplit(v, &g_FCh[base+j], &g_FCl[base+j]);
    } else if (j < 72) {
        int c = 68 + (j-68);
        g_FCh[base+c] = g_Fh[base+c]; g_FCl[base+c] = g_Fl[base+c];
    } else {
        int c = 136 + (j-72);
        g_FCh[base+c] = g_Fh[base+c]; g_FCl[base+c] = g_Fl[base+c];
    }
}

__global__ void build_rh1() {
    int idx = blockIdx.x*256 + threadIdx.x;
    if (idx >= NB*64) return;
    int c = idx & 63, row = idx >> 6;
    float v = g_UR[(long)row*128 + 64 + c] * g_H1[(long)row*64 + c];
    long a = (long)row*CF1 + 64 + c;
    bsplit(v, &g_FCh[a], &g_FCl[a]);
}

// ---------------- tensor-core graph propagation (3-stage cp.async) ------------
// dynamic smem layout per stage (elems): Ah 3072 | Al 3072 | Bh 2176 | Bl 2176
#define P_STG 10496
__global__ void __launch_bounds__(256) prop_tc(int bufSel, int CF, int src_off,
                                               int d1, int d2, int Psub) {
    extern __shared__ __nv_bfloat16 dynsm[];
    const __nv_bfloat16* Fh = bufSel ? g_FCh : g_Fh;
    const __nv_bfloat16* Fl = bufSel ? g_FCl : g_Fl;
    __nv_bfloat16* Oh = bufSel ? g_FCh : g_Fh;
    __nv_bfloat16* Ol = bufSel ? g_FCl : g_Fl;
    int tid = threadIdx.x, lane = tid & 31, warp = tid >> 5;
    int m0 = blockIdx.y*128, n0 = blockIdx.x*128;
    int wm = warp >> 2, wn = warp & 3;
    long rowStride = (long)B_*CF;

    float acc[4][4][4];
    #pragma unroll
    for (int i=0;i<4;i++)
        #pragma unroll
        for (int j=0;j<4;j++)
            #pragma unroll
            for (int e=0;e<4;e++) acc[i][j][e]=0.f;

    int aRow = tid >> 1, aSeg = (tid & 1)*8;
    long aBase = (long)(m0 + aRow)*800 + aSeg;
    int kr0 = tid >> 5,        cc0 = (tid & 31)*4;
    int kr1 = (tid+256) >> 5,  cc1 = (tid & 31)*4;
    int j0g = n0 + cc0, j1g = n0 + cc1;
    int bo0 = j0g/Psub, co0 = j0g - bo0*Psub;
    int bo1 = j1g/Psub, co1 = j1g - bo1*Psub;
    long bOff0 = (long)bo0*CF + src_off + co0;
    long bOff1 = (long)bo1*CF + src_off + co1;

    auto issue = [&](int k0, int s) {
        __nv_bfloat16* bp = dynsm + s*P_STG;
        cp16(bp + aRow*24 + aSeg,        g_A2h + aBase + k0);
        cp16(bp + 3072 + aRow*24 + aSeg, g_A2l + aBase + k0);
        long a0 = (long)(k0+kr0)*rowStride + bOff0;
        long a1 = (long)(k0+kr1)*rowStride + bOff1;
        cp8(bp + 6144 + kr0*136 + cc0, Fh + a0);
        cp8(bp + 8320 + kr0*136 + cc0, Fl + a0);
        cp8(bp + 6144 + kr1*136 + cc1, Fh + a1);
        cp8(bp + 8320 + kr1*136 + cc1, Fl + a1);
        cp_commit();
    };

    int grp = lane >> 3, rr = lane & 7;
    int arow = ((grp & 1) ? 8 : 0) + rr;
    int acol = (grp & 2) ? 8 : 0;
    int brow = lane & 15;

    issue(0, 0); issue(16, 1);
    for (int c = 0; c < 50; c++) {
        if (c < 49) asm volatile("cp.async.wait_group 1;");
        else        asm volatile("cp.async.wait_group 0;");
        __syncthreads();
        if (c + 2 < 50) issue((c+2)*16, (c+2)%3);
        __nv_bfloat16* bp = dynsm + (c%3)*P_STG;
        unsigned fah[4][4], fal[4][4], fbh[4][2], fbl[4][2];
        #pragma unroll
        for (int mi=0; mi<4; mi++) {
            ldsm_x4(fah[mi], su(bp + (wm*64 + mi*16 + arow)*24 + acol));
            ldsm_x4(fal[mi], su(bp + 3072 + (wm*64 + mi*16 + arow)*24 + acol));
        }
        #pragma unroll
        for (int ni=0; ni<4; ni++) {
            ldsm_x2t(fbh[ni], su(bp + 6144 + brow*136 + wn*32 + ni*8));
            ldsm_x2t(fbl[ni], su(bp + 8320 + brow*136 + wn*32 + ni*8));
        }
        #pragma unroll
        for (int mi=0; mi<4; mi++)
            #pragma unroll
            for (int ni=0; ni<4; ni++) {
                mma_bf16(acc[mi][ni], fah[mi], fbh[ni]);
                mma_bf16(acc[mi][ni], fah[mi], fbl[ni]);
                mma_bf16(acc[mi][ni], fal[mi], fbh[ni]);
            }
    }

    #pragma unroll
    for (int mi=0; mi<4; mi++)
        #pragma unroll
        for (int ni=0; ni<4; ni++) {
            int rb = m0 + wm*64 + mi*16 + (lane >> 2);
            int cb = n0 + wn*32 + ni*8 + 2*(lane & 3);
            int bo = cb / Psub, co = cb - bo*Psub;
            #pragma unroll
            for (int hh=0; hh<2; hh++) {
                int gr = rb + hh*8;
                if (gr >= 1600) continue;
                int gm  = (gr < 800) ? gr : gr - 800;
                int off = (gr < 800) ? d1 : d2;
                long a = (long)gm*rowStride + (long)bo*CF + off + co;
                float v0 = acc[mi][ni][2*hh], v1 = acc[mi][ni][2*hh+1];
                __nv_bfloat16 h0 = __float2bfloat16(v0);
                __nv_bfloat16 h1 = __float2bfloat16(v1);
                __nv_bfloat16 l0 = __float2bfloat16(v0 - __bfloat162float(h0));
                __nv_bfloat16 l1 = __float2bfloat16(v1 - __bfloat162float(h1));
                *(__nv_bfloat162*)&Oh[a] = __halves2bfloat162(h0, h1);
                *(__nv_bfloat162*)&Ol[a] = __halves2bfloat162(l0, l1);
            }
        }
}

// ---------------- tensor-core projection (3-stage cp.async) -------------------
template<int NO, int MODE>
__global__ void __launch_bounds__(256) proj_tc(int srcMode, int CF, int KT, int wsel,
                                               const float* __restrict__ bias, int hsel) {
    extern __shared__ __nv_bfloat16 dynsm[];
    const __nv_bfloat16* Wh = (MODE==0) ? g_WGh[wsel] : g_WCh[wsel];
    const __nv_bfloat16* Wl = (MODE==0) ? g_WGl[wsel] : g_WCl[wsel];
    constexpr int WN = NO/32;
    constexpr int WM = 8/WN;
    constexpr int MT = (128/WM)/16;
    constexpr int BROW = NO + 8;
    constexpr int BSZ  = 16*BROW;
    constexpr int STG  = 6144 + 2*BSZ;
    int tid = threadIdx.x, lane = tid & 31, warp = tid >> 5;
    long row0 = (long)blockIdx.x*128;
    int wm = warp / WN, wn = warp % WN;
    float acc[MT][4][4];
    #pragma unroll
    for (int i=0;i<MT;i++)
        #pragma unroll
        for (int j=0;j<4;j++)
            #pragma unroll
            for (int e=0;e<4;e++) acc[i][j][e]=0.f;

    int aRow = tid >> 1, aSeg = (tid & 1)*8;
    long aBase = (row0 + aRow)*CF + aSeg;

    auto issue = [&](int k0, int s) {
        const __nv_bfloat16 *Sh, *Sl;
        if (srcMode == 0)       { Sh = g_Fh;  Sl = g_Fl; }
        else if (srcMode == 1)  { Sh = g_FCh; Sl = g_FCl; }
        else if ((k0 >> 6) & 1) { Sh = g_FCh; Sl = g_FCl; }
        else                    { Sh = g_Fh;  Sl = g_Fl; }
        __nv_bfloat16* bp = dynsm + s*STG;
        cp16(bp + aRow*24 + aSeg,        Sh + aBase + k0);
        cp16(bp + 3072 + aRow*24 + aSeg, Sl + aBase + k0);
        if (NO == 128) {
            int wr = tid >> 4, wc = (tid & 15)*8;
            long a = (long)(k0+wr)*NO + wc;
            cp16(bp + 6144 + wr*BROW + wc,       Wh + a);
            cp16(bp + 6144 + BSZ + wr*BROW + wc, Wl + a);
        } else if (tid < 128) {
            int wr = tid >> 3, wc = (tid & 7)*8;
            long a = (long)(k0+wr)*NO + wc;
            cp16(bp + 6144 + wr*BROW + wc,       Wh + a);
            cp16(bp + 6144 + BSZ + wr*BROW + wc, Wl + a);
        }
        cp_commit();
    };

    int grp = lane >> 3, rr = lane & 7;
    int arow = ((grp & 1) ? 8 : 0) + rr;
    int acol = (grp & 2) ? 8 : 0;
    int brow = lane & 15;

    int NC = KT / 16;
    issue(0, 0); issue(16, 1);
    for (int c = 0; c < NC; c++) {
        if (c < NC-1) asm volatile("cp.async.wait_group 1;");
        else          asm volatile("cp.async.wait_group 0;");
        __syncthreads();
        if (c + 2 < NC) issue((c+2)*16, (c+2)%3);
        __nv_bfloat16* bp = dynsm + (c%3)*STG;
        unsigned fah[MT][4], fal[MT][4], fbh[4][2], fbl[4][2];
        #pragma unroll
        for (int mi=0; mi<MT; mi++) {
            ldsm_x4(fah[mi], su(bp + (wm*(MT*16) + mi*16 + arow)*24 + acol));
            ldsm_x4(fal[mi], su(bp + 3072 + (wm*(MT*16) + mi*16 + arow)*24 + acol));
        }
        #pragma unroll
        for (int ni=0; ni<4; ni++) {
            int cc = wn*32 + ni*8;
            ldsm_x2t(fbh[ni], su(bp + 6144 + brow*BROW + cc));
            ldsm_x2t(fbl[ni], su(bp + 6144 + BSZ + brow*BROW + cc));
        }
        #pragma unroll
        for (int mi=0; mi<MT; mi++)
            #pragma unroll
            for (int ni=0; ni<4; ni++) {
                mma_bf16(acc[mi][ni], fah[mi], fbh[ni]);
                mma_bf16(acc[mi][ni], fah[mi], fbl[ni]);
                mma_bf16(acc[mi][ni], fal[mi], fbh[ni]);
            }
    }

    float* Hb = hsel ? g_H1 : g_H0;
    #pragma unroll
    for (int mi=0; mi<MT; mi++)
        #pragma unroll
        for (int ni=0; ni<4; ni++) {
            long rb = row0 + wm*(MT*16) + mi*16 + (lane >> 2);
            int  cb = wn*32 + ni*8 + 2*(lane & 3);
            #pragma unroll
            for (int e=0; e<4; e++) {
                long row = rb + ((e >= 2) ? 8 : 0);
                int  c   = cb + (e & 1);
                float v = acc[mi][ni][e] + bias[c];
                if (MODE == 0) {
                    g_UR[row*128 + c] = 1.f/(1.f + expf(-v));
                } else {
                    float cv = tanhf(v);
                    float u  = g_UR[row*128 + c];
                    float h  = Hb[row*64 + c];
                    Hb[row*64 + c] = (1.f - u)*h + u*cv;
                }
            }
        }
}

// ---------------- decoder memory attention + output projection ----------------
__global__ void query_kernel(const float* __restrict__ Wa) {
    int b = blockIdx.x, tid = threadIdx.x;
    float p[8];
    #pragma unroll
    for (int d = 0; d < 8; d++) p[d] = 0.f;
    for (int idx = tid; idx < N_*H_; idx += 256) {
        int n = idx >> 6, j = idx & 63;
        float v = g_H1[(long)(n*B_ + b)*64 + j];
        const float* w = Wa + (long)idx*8;
        #pragma unroll
        for (int d = 0; d < 8; d++) p[d] += v*w[d];
    }
    #pragma unroll
    for (int d = 0; d < 8; d++)
        for (int off = 16; off > 0; off >>= 1) p[d] += __shfl_down_sync(0xffffffffu, p[d], off);
    __shared__ float sm[8][8];
    int w = tid >> 5, l = tid & 31;
    if (l == 0) { for (int d = 0; d < 8; d++) sm[w][d] = p[d]; }
    __syncthreads();
    if (tid < 8) {
        float s = 0.f;
        for (int ww = 0; ww < 8; ww++) s += sm[ww][tid];
        g_Q[b*8 + tid] = s;
    }
}

__global__ void attm_kernel(const float* __restrict__ mem, const float* __restrict__ fcw) {
    int b = blockIdx.x, tid = threadIdx.x;
    __shared__ float am[8];
    if (tid == 0) {
        float q[8];
        for (int d = 0; d < 8; d++) q[d] = g_Q[b*8 + d];
        float s[4]; float mx = -1e30f;
        for (int m = 0; m < 4; m++) {
            float a = 0.f;
            for (int d = 0; d < 8; d++) a += q[d]*mem[m*8 + d];
            s[m] = a; mx = fmaxf(mx, a);
        }
        float den = 0.f;
        for (int m = 0; m < 4; m++) { s[m] = expf(s[m]-mx); den += s[m]; }
        for (int d = 0; d < 8; d++) {
            float a = 0.f;
            for (int m = 0; m < 4; m++) a += (s[m]/den)*mem[m*8 + d];
            am[d] = a;
        }
    }
    __syncthreads();
    for (int i = tid; i < N_*8; i += 256) {
        float s = 0.f;
        #pragma unroll
        for (int d = 0; d < 8; d++) s += am[d]*fcw[(long)d*(N_*8) + i];
        g_ATTM[(long)b*(N_*8) + i] = s;
    }
}

__global__ void out_kernel(const float* __restrict__ pW, const float* __restrict__ pb,
                           float* __restrict__ outp, int s) {
    int row = blockIdx.x*256 + threadIdx.x;
    if (row >= NB) return;
    int b = row % B_, n = row / B_;
    float a0 = pb[0], a1 = pb[1];
    const float* h = g_H1 + (long)row*64;
    #pragma unroll
    for (int j = 0; j < 64; j++) { float v = h[j]; a0 += v*pW[j*2]; a1 += v*pW[j*2+1]; }
    const float* at = g_ATTM + (long)b*(N_*8) + n*8;
    #pragma unroll
    for (int d = 0; d < 8; d++) { float v = at[d]; a0 += v*pW[(64+d)*2]; a1 += v*pW[(64+d)*2+1]; }
    a0 = fmaxf(a0, 0.f); a1 = fmaxf(a1, 0.f);
    g_GO[row*2] = a0; g_GO[row*2+1] = a1;
    long o = ((long)(b*HOR_ + s)*N_ + n)*CIN_;
    outp[o] = a0; outp[o+1] = a1;
}

// ---------------- orchestration ----------------
extern "C" void kernel_launch(void* const* d_in, const int* in_sizes, int n_in,
                              void* d_out, int out_size) {
    (void)in_sizes; (void)n_in; (void)out_size;
    const float* x_seq = (const float*)d_in[0];
    const float* t_x   = (const float*)d_in[1];
    const float* t_y   = (const float*)d_in[2];
    const float* G     = (const float*)d_in[3];
    const float* eWg0  = (const float*)d_in[4];  const float* ebg0 = (const float*)d_in[5];
    const float* eWc0  = (const float*)d_in[6];  const float* ebc0 = (const float*)d_in[7];
    const float* eWg1  = (const float*)d_in[8];  const float* ebg1 = (const float*)d_in[9];
    const float* eWc1  = (const float*)d_in[10]; const float* ebc1 = (const float*)d_in[11];
    const float* dWg0  = (const float*)d_in[12]; const float* dbg0 = (const float*)d_in[13];
    const float* dWc0  = (const float*)d_in[14]; const float* dbc0 = (const float*)d_in[15];
    const float* dWg1  = (const float*)d_in[16]; const float* dbg1 = (const float*)d_in[17];
    const float* dWc1  = (const float*)d_in[18]; const float* dbc1 = (const float*)d_in[19];
    const float* mW1   = (const float*)d_in[20]; const float* mb1  = (const float*)d_in[21];
    const float* mW2   = (const float*)d_in[22]; const float* mb2  = (const float*)d_in[23];
    const float* mem   = (const float*)d_in[24];
    const float* Wa    = (const float*)d_in[25];
    const float* fcw   = (const float*)d_in[26];
    const float* projW = (const float*)d_in[27];
    const float* projb = (const float*)d_in[28];
    float* outp = (float*)d_out;

    const int PROP_SMEM  = 3*P_STG*2;                 // 62976 B
    const int PROJ128_SMEM = 3*(6144 + 2*16*136)*2;   // 62976 B
    const int PROJ64_SMEM  = 3*(6144 + 2*16*72)*2;    // 50688 B
    cudaFuncSetAttribute(prop_tc, cudaFuncAttributeMaxDynamicSharedMemorySize, PROP_SMEM);
    cudaFuncSetAttribute(proj_tc<128,0>, cudaFuncAttributeMaxDynamicSharedMemorySize, PROJ128_SMEM);
    cudaFuncSetAttribute(proj_tc<64,1>, cudaFuncAttributeMaxDynamicSharedMemorySize, PROJ64_SMEM);

    transpose_kernel<<<dim3(25,25), dim3(32,32)>>>(G);
    g2_kernel<<<dim3(7,7), 256>>>();
    split_a2<<<(MPAD*800+255)/256, 256>>>();

    auto fold = [](const float* W, int isGate, int widx, int P, int O) {
        int KT = ((3*P + 15)/16)*16;
        fold_split<<<(KT*O+255)/256, 256>>>(W, isGate, widx, P, O, KT);
    };
    fold(eWg0,1,0,68,128);  fold(eWc0,0,0,68,64);
    fold(eWg1,1,1,128,128); fold(eWc1,0,1,128,64);
    fold(dWg0,1,2,68,128);  fold(dWc0,0,2,68,64);
    fold(dWg1,1,3,128,128); fold(dWc1,0,3,128,64);

    mlp_kernel<<<B_*T_,   256>>>(t_x, mW1, mb1, mW2, mb2, 0);
    mlp_kernel<<<B_*HOR_, 256>>>(t_y, mW1, mb1, mW2, mb2, 1);
    zero_state<<<(NB*H_+255)/256, 256>>>();

    auto cell0 = [&](int wsel, const float* bg, const float* bc) {
        prop_tc<<<dim3(34,13), 256, PROP_SMEM>>>(0, CF0, 0, 68, 136, 68);
        proj_tc<128,0><<<NB/128, 256, PROJ128_SMEM>>>(0, CF0, 208, wsel, bg, 0);
        build_fc0<<<(NB*76+255)/256, 256>>>();
        prop_tc<<<dim3(32,13), 256, PROP_SMEM>>>(1, CF0, 4, 72, 140, 64);
        proj_tc<64,1><<<NB/128, 256, PROJ64_SMEM>>>(1, CF0, 208, wsel, bc, 0);
    };
    auto cell1 = [&](int wsel, const float* bg, const float* bc) {
        prop_tc<<<dim3(64,13), 256, PROP_SMEM>>>(0, CF1, 0, 128, 256, 128);
        proj_tc<128,0><<<NB/128, 256, PROJ128_SMEM>>>(0, CF1, 384, wsel, bg, 1);
        build_rh1<<<(NB*64+255)/256, 256>>>();
        prop_tc<<<dim3(32,13), 256, PROP_SMEM>>>(1, CF1, 64, 192, 320, 64);
        proj_tc<64,1><<<NB/128, 256, PROJ64_SMEM>>>(2, CF1, 384, wsel, bc, 1);
    };

    // encoder
    for (int t = 0; t < T_; t++) {
        build_xh0<<<(NB*68+255)/256, 256>>>(x_seq, t, 0);
        cell0(0, ebg0, ebc0);
        build_xh1<<<(NB*128+255)/256, 256>>>();
        cell1(1, ebg1, ebc1);
    }
    // decoder
    for (int s = 0; s < HOR_; s++) {
        build_xh0<<<(NB*68+255)/256, 256>>>(x_seq, s, 1);
        cell0(2, dbg0, dbc0);
        build_xh1<<<(NB*128+255)/256, 256>>>();
        cell1(3, dbg1, dbc1);
        query_kernel<<<B_, 256>>>(Wa);
        attm_kernel<<<B_, 256>>>(mem, fcw);
        out_kernel<<<NB/256, 256>>>(projW, projb, outp, s);
    }
}

// round 12
// speedup vs baseline: 1.5294x; 1.3851x over previous
#include <cuda_runtime.h>
#include <cuda_fp16.h>
#include <stdint.h>
#include <math.h>

#define B_    64
#define T_    12
#define N_    800
#define CIN_  2
#define H_    64
#define HOR_  12
#define TC_H  2
#define KAPPA_ 0.05f
#define NB    (N_*B_)
#define CF0   208
#define CF1   384
#define MPAD  1664

// ---------------- device scratch ----------------
__device__ float g_A2[1600*800];
__device__ __align__(16) __half g_A2h[MPAD*800];   // hi (fp16 split-2, static)
__device__ __align__(16) __half g_A2l[MPAD*800];   // lo
__device__ float g_EMBX[B_*T_*N_*TC_H];
__device__ float g_EMBY[B_*HOR_*N_*TC_H];
__device__ float g_H0[NB*H_];
__device__ float g_H1[NB*H_];
__device__ float g_UR[NB*128];
__device__ float g_GO[NB*CIN_];
__device__ float g_Q [B_*8];
__device__ float g_ATTM[B_*N_*8];
__device__ __align__(16) __half g_F [NB*384];      // features: SINGLE fp16
__device__ __align__(16) __half g_FC[NB*384];
__device__ __align__(16) __half g_WGh[4][384*128]; // weights: fp16 split-2
__device__ __align__(16) __half g_WGl[4][384*128];
__device__ __align__(16) __half g_WCh[4][384*64];
__device__ __align__(16) __half g_WCl[4][384*64];

// ---------------- helpers ----------------
__device__ __forceinline__ unsigned su(void* p) {
    return (unsigned)__cvta_generic_to_shared(p);
}
__device__ __forceinline__ void cp16(void* dst, const void* src) {
    asm volatile("cp.async.ca.shared.global [%0],[%1],16;" :: "r"(su(dst)), "l"(src));
}
__device__ __forceinline__ void cp8(void* dst, const void* src) {
    asm volatile("cp.async.ca.shared.global [%0],[%1],8;" :: "r"(su(dst)), "l"(src));
}
__device__ __forceinline__ void cp_commit() {
    asm volatile("cp.async.commit_group;");
}
__device__ __forceinline__ void ldsm_x4(unsigned* r, unsigned addr) {
    asm volatile("ldmatrix.sync.aligned.m8n8.x4.shared.b16 {%0,%1,%2,%3},[%4];"
        : "=r"(r[0]),"=r"(r[1]),"=r"(r[2]),"=r"(r[3]) : "r"(addr));
}
__device__ __forceinline__ void ldsm_x2t(unsigned* r, unsigned addr) {
    asm volatile("ldmatrix.sync.aligned.m8n8.x2.trans.shared.b16 {%0,%1},[%2];"
        : "=r"(r[0]),"=r"(r[1]) : "r"(addr));
}
__device__ __forceinline__ void mma_f16(float* c, const unsigned* a, const unsigned* b) {
    asm volatile("mma.sync.aligned.m16n8k16.row.col.f32.f16.f16.f32 "
        "{%0,%1,%2,%3},{%4,%5,%6,%7},{%8,%9},{%0,%1,%2,%3};"
        : "+f"(c[0]),"+f"(c[1]),"+f"(c[2]),"+f"(c[3])
        : "r"(a[0]),"r"(a[1]),"r"(a[2]),"r"(a[3]),"r"(b[0]),"r"(b[1]));
}
__device__ __forceinline__ void hsplit(float v, __half* ph, __half* pl) {
    __half h = __float2half_rn(v);
    *ph = h;
    *pl = __float2half_rn(v - __half2float(h));
}

// ---------------- setup kernels ----------------
__global__ void transpose_kernel(const float* __restrict__ G) {
    __shared__ float t[32][33];
    int x = blockIdx.x*32 + threadIdx.x, y = blockIdx.y*32 + threadIdx.y;
    t[threadIdx.y][threadIdx.x] = G[y*N_ + x];
    __syncthreads();
    int x2 = blockIdx.y*32 + threadIdx.x, y2 = blockIdx.x*32 + threadIdx.y;
    g_A2[y2*N_ + x2] = t[threadIdx.x][threadIdx.y];
}

__global__ void __launch_bounds__(256) g2_kernel() {
    __shared__ float As[8][128], Bs[8][128];
    int tid = threadIdx.x;
    int i0 = blockIdx.y*128, j0 = blockIdx.x*128;
    int ty = tid>>4, tx = tid&15, rl = ty*4, cl = tx*4;
    int ar = tid>>1, ac = (tid&1)*4;
    int bk = tid>>5, bj = (tid&31)*4;
    float acc[8][8];
    #pragma unroll
    for (int i=0;i<8;i++) {
        #pragma unroll
        for (int j=0;j<8;j++) acc[i][j]=0.f;
    }
    for (int k0=0;k0<N_;k0+=8) {
        float4 av = make_float4(0,0,0,0);
        if (i0+ar < N_) av = *(const float4*)&g_A2[(long)(i0+ar)*N_ + k0+ac];
        As[ac+0][ar]=av.x; As[ac+1][ar]=av.y; As[ac+2][ar]=av.z; As[ac+3][ar]=av.w;
        float4 bv = make_float4(0,0,0,0);
        if (j0+bj < N_) bv = *(const float4*)&g_A2[(long)(k0+bk)*N_ + j0+bj];
        *(float4*)&Bs[bk][bj] = bv;
        __syncthreads();
        #pragma unroll
        for (int kk=0;kk<8;kk++) {
            float a[8], b[8];
            *(float4*)a     = *(const float4*)&As[kk][rl];
            *(float4*)(a+4) = *(const float4*)&As[kk][rl+64];
            *(float4*)b     = *(const float4*)&Bs[kk][cl];
            *(float4*)(b+4) = *(const float4*)&Bs[kk][cl+64];
            #pragma unroll
            for (int i=0;i<8;i++) {
                #pragma unroll
                for (int j=0;j<8;j++) acc[i][j] += a[i]*b[j];
            }
        }
        __syncthreads();
    }
    #pragma unroll
    for (int i=0;i<8;i++) {
        int r = i0 + (i<4 ? rl+i : 64+rl+i-4);
        if (r >= N_) continue;
        #pragma unroll
        for (int j=0;j<8;j++) {
            int c = j0 + (j<4 ? cl+j : 64+cl+j-4);
            if (c >= N_) continue;
            g_A2[(long)(N_+r)*N_ + c] = 2.f*acc[i][j] - (r==c ? 1.f : 0.f);
        }
    }
}

__global__ void split_a2() {
    int i = blockIdx.x*256 + threadIdx.x;
    if (i >= MPAD*800) return;
    float v = (i < 1600*800) ? g_A2[i] : 0.f;
    hsplit(v, &g_A2h[i], &g_A2l[i]);
}

__global__ void fold_split(const float* __restrict__ W, int isGate, int widx,
                           int P, int O, int KT) {
    int idx = blockIdx.x*256 + threadIdx.x;
    if (idx >= KT*O) return;
    int row = idx / O, o = idx % O;
    float v = 0.f;
    if (row < 3*P) {
        int k = row / P, p = row % P;
        if (k == 0) v = W[idx] + KAPPA_*(W[(P+p)*O + o] + W[(2*P+p)*O + o]);
        else        v = (1.f - KAPPA_)*W[idx];
    }
    if (isGate) hsplit(v, &g_WGh[widx][idx], &g_WGl[widx][idx]);
    else        hsplit(v, &g_WCh[widx][idx], &g_WCl[widx][idx]);
}

__global__ void mlp_kernel(const float* __restrict__ Tin,
                           const float* __restrict__ W1, const float* __restrict__ b1,
                           const float* __restrict__ W2, const float* __restrict__ b2,
                           int dsel) {
    float* out = dsel ? g_EMBY : g_EMBX;
    int r = blockIdx.x, tid = threadIdx.x;
    __shared__ float tin[60];
    __shared__ float hid[10];
    if (tid < 60) tin[tid] = Tin[(long)r*60 + tid];
    __syncthreads();
    if (tid < 10) {
        float s = b1[tid];
        for (int i = 0; i < 60; i++) s += tin[i]*W1[i*10 + tid];
        hid[tid] = s;
    }
    __syncthreads();
    for (int o = tid; o < N_*TC_H; o += 256) {
        float s = b2[o];
        #pragma unroll
        for (int j = 0; j < 10; j++) s += hid[j]*W2[j*(N_*TC_H) + o];
        out[(long)r*(N_*TC_H) + o] = s;
    }
}

__global__ void zero_state() {
    int i = blockIdx.x*256 + threadIdx.x;
    if (i < NB*H_) { g_H0[i] = 0.f; g_H1[i] = 0.f; }
    if (i < NB*CIN_) g_GO[i] = 0.f;
    if (i < NB*4) {
        int row = i >> 2, c = 204 + (i & 3);
        long a = (long)row*CF0 + c;
        __half z = __float2half_rn(0.f);
        g_F[a] = z; g_FC[a] = z;
    }
}

// ---------------- feature builders (single fp16 writes) -----------------------
__global__ void build_xh0(const float* __restrict__ xs, int t, int isDec) {
    int idx = blockIdx.x*256 + threadIdx.x;
    if (idx >= NB*68) return;
    int c = idx % 68, row = idx / 68;
    int b = row % B_, n = row / B_;
    float v;
    if (isDec) {
        if (c < 2)      v = g_GO[row*2 + c];
        else if (c < 4) v = g_EMBY[(long)(b*HOR_ + t)*(N_*TC_H) + n*TC_H + (c-2)];
        else            v = g_H0[(long)row*64 + (c-4)];
    } else {
        if (c < 2)      v = xs[((long)(b*T_ + t)*N_ + n)*CIN_ + c];
        else if (c < 4) v = g_EMBX[(long)(b*T_ + t)*(N_*TC_H) + n*TC_H + (c-2)];
        else            v = g_H0[(long)row*64 + (c-4)];
    }
    g_F[(long)row*CF0 + c] = __float2half_rn(v);
}

__global__ void build_xh1() {
    int idx = blockIdx.x*256 + threadIdx.x;
    if (idx >= NB*128) return;
    int c = idx % 128, row = idx / 128;
    float v = (c < 64) ? g_H0[(long)row*64 + c] : g_H1[(long)row*64 + (c-64)];
    g_F[(long)row*CF1 + c] = __float2half_rn(v);
}

__global__ void build_fc0() {
    int idx = blockIdx.x*256 + threadIdx.x;
    if (idx >= NB*76) return;
    int j = idx % 76, row = idx / 76;
    long base = (long)row*CF0;
    if (j < 4) {
        g_FC[base+j] = g_F[base+j];
    } else if (j < 68) {
        int c = j - 4;
        float v = g_UR[(long)row*128 + 64 + c] * g_H0[(long)row*64 + c];
        g_FC[base+j] = __float2half_rn(v);
    } else if (j < 72) {
        int c = 68 + (j-68);
        g_FC[base+c] = g_F[base+c];
    } else {
        int c = 136 + (j-72);
        g_FC[base+c] = g_F[base+c];
    }
}

__global__ void build_rh1() {
    int idx = blockIdx.x*256 + threadIdx.x;
    if (idx >= NB*64) return;
    int c = idx & 63, row = idx >> 6;
    float v = g_UR[(long)row*128 + 64 + c] * g_H1[(long)row*64 + c];
    g_FC[(long)row*CF1 + 64 + c] = __float2half_rn(v);
}

// ---------------- tensor-core graph propagation (fp16 2-product) --------------
// stage (half elems): Ah 3072 | Al 3072 | B 2176
#define P_STG 8320
__global__ void __launch_bounds__(256) prop_tc(int bufSel, int CF, int src_off,
                                               int d1, int d2, int Psub) {
    extern __shared__ __half dynsm[];
    const __half* F = bufSel ? g_FC : g_F;
    __half* O = bufSel ? g_FC : g_F;
    int tid = threadIdx.x, lane = tid & 31, warp = tid >> 5;
    int m0 = blockIdx.y*128, n0 = blockIdx.x*128;
    int wm = warp >> 2, wn = warp & 3;
    long rowStride = (long)B_*CF;

    float acc[4][4][4];
    #pragma unroll
    for (int i=0;i<4;i++)
        #pragma unroll
        for (int j=0;j<4;j++)
            #pragma unroll
            for (int e=0;e<4;e++) acc[i][j][e]=0.f;

    int aRow = tid >> 1, aSeg = (tid & 1)*8;
    long aBase = (long)(m0 + aRow)*800 + aSeg;
    int kr0 = tid >> 5,        cc0 = (tid & 31)*4;
    int kr1 = (tid+256) >> 5,  cc1 = (tid & 31)*4;
    int j0g = n0 + cc0, j1g = n0 + cc1;
    int bo0 = j0g/Psub, co0 = j0g - bo0*Psub;
    int bo1 = j1g/Psub, co1 = j1g - bo1*Psub;
    long bOff0 = (long)bo0*CF + src_off + co0;
    long bOff1 = (long)bo1*CF + src_off + co1;

    auto issue = [&](int k0, int s) {
        __half* bp = dynsm + s*P_STG;
        cp16(bp + aRow*24 + aSeg,        g_A2h + aBase + k0);
        cp16(bp + 3072 + aRow*24 + aSeg, g_A2l + aBase + k0);
        cp8(bp + 6144 + kr0*136 + cc0, F + (long)(k0+kr0)*rowStride + bOff0);
        cp8(bp + 6144 + kr1*136 + cc1, F + (long)(k0+kr1)*rowStride + bOff1);
        cp_commit();
    };

    int grp = lane >> 3, rr = lane & 7;
    int arow = ((grp & 1) ? 8 : 0) + rr;
    int acol = (grp & 2) ? 8 : 0;
    int brow = lane & 15;

    issue(0, 0); issue(16, 1);
    for (int c = 0; c < 50; c++) {
        if (c < 49) asm volatile("cp.async.wait_group 1;");
        else        asm volatile("cp.async.wait_group 0;");
        __syncthreads();
        if (c + 2 < 50) issue((c+2)*16, (c+2)%3);
        __half* bp = dynsm + (c%3)*P_STG;
        unsigned fah[4][4], fal[4][4], fb[4][2];
        #pragma unroll
        for (int mi=0; mi<4; mi++) {
            ldsm_x4(fah[mi], su(bp + (wm*64 + mi*16 + arow)*24 + acol));
            ldsm_x4(fal[mi], su(bp + 3072 + (wm*64 + mi*16 + arow)*24 + acol));
        }
        #pragma unroll
        for (int ni=0; ni<4; ni++)
            ldsm_x2t(fb[ni], su(bp + 6144 + brow*136 + wn*32 + ni*8));
        #pragma unroll
        for (int mi=0; mi<4; mi++)
            #pragma unroll
            for (int ni=0; ni<4; ni++) {
                mma_f16(acc[mi][ni], fah[mi], fb[ni]);
                mma_f16(acc[mi][ni], fal[mi], fb[ni]);
            }
    }

    #pragma unroll
    for (int mi=0; mi<4; mi++)
        #pragma unroll
        for (int ni=0; ni<4; ni++) {
            int rb = m0 + wm*64 + mi*16 + (lane >> 2);
            int cb = n0 + wn*32 + ni*8 + 2*(lane & 3);
            int bo = cb / Psub, co = cb - bo*Psub;
            #pragma unroll
            for (int hh=0; hh<2; hh++) {
                int gr = rb + hh*8;
                if (gr >= 1600) continue;
                int gm  = (gr < 800) ? gr : gr - 800;
                int off = (gr < 800) ? d1 : d2;
                long a = (long)gm*rowStride + (long)bo*CF + off + co;
                *(__half2*)&O[a] = __halves2half2(
                    __float2half_rn(acc[mi][ni][2*hh]),
                    __float2half_rn(acc[mi][ni][2*hh+1]));
            }
        }
}

// ---------------- tensor-core projection (fp16 2-product) ---------------------
template<int NO, int MODE>
__global__ void __launch_bounds__(256) proj_tc(int srcMode, int CF, int KT, int wsel,
                                               const float* __restrict__ bias, int hsel) {
    extern __shared__ __half dynsm[];
    const __half* Wh = (MODE==0) ? g_WGh[wsel] : g_WCh[wsel];
    const __half* Wl = (MODE==0) ? g_WGl[wsel] : g_WCl[wsel];
    constexpr int WN = NO/32;
    constexpr int WM = 8/WN;
    constexpr int MT = (128/WM)/16;
    constexpr int BROW = NO + 8;
    constexpr int BSZ  = 16*BROW;
    constexpr int STG  = 3072 + 2*BSZ;
    int tid = threadIdx.x, lane = tid & 31, warp = tid >> 5;
    long row0 = (long)blockIdx.x*128;
    int wm = warp / WN, wn = warp % WN;
    float acc[MT][4][4];
    #pragma unroll
    for (int i=0;i<MT;i++)
        #pragma unroll
        for (int j=0;j<4;j++)
            #pragma unroll
            for (int e=0;e<4;e++) acc[i][j][e]=0.f;

    int aRow = tid >> 1, aSeg = (tid & 1)*8;
    long aBase = (row0 + aRow)*CF + aSeg;

    auto issue = [&](int k0, int s) {
        const __half* S;
        if (srcMode == 0)       S = g_F;
        else if (srcMode == 1)  S = g_FC;
        else if ((k0 >> 6) & 1) S = g_FC;
        else                    S = g_F;
        __half* bp = dynsm + s*STG;
        cp16(bp + aRow*24 + aSeg, S + aBase + k0);
        if (NO == 128) {
            int wr = tid >> 4, wc = (tid & 15)*8;
            long a = (long)(k0+wr)*NO + wc;
            cp16(bp + 3072 + wr*BROW + wc,       Wh + a);
            cp16(bp + 3072 + BSZ + wr*BROW + wc, Wl + a);
        } else if (tid < 128) {
            int wr = tid >> 3, wc = (tid & 7)*8;
            long a = (long)(k0+wr)*NO + wc;
            cp16(bp + 3072 + wr*BROW + wc,       Wh + a);
            cp16(bp + 3072 + BSZ + wr*BROW + wc, Wl + a);
        }
        cp_commit();
    };

    int grp = lane >> 3, rr = lane & 7;
    int arow = ((grp & 1) ? 8 : 0) + rr;
    int acol = (grp & 2) ? 8 : 0;
    int brow = lane & 15;

    int NC = KT / 16;
    issue(0, 0); issue(16, 1);
    for (int c = 0; c < NC; c++) {
        if (c < NC-1) asm volatile("cp.async.wait_group 1;");
        else          asm volatile("cp.async.wait_group 0;");
        __syncthreads();
        if (c + 2 < NC) issue((c+2)*16, (c+2)%3);
        __half* bp = dynsm + (c%3)*STG;
        unsigned fa[MT][4], fwh[4][2], fwl[4][2];
        #pragma unroll
        for (int mi=0; mi<MT; mi++)
            ldsm_x4(fa[mi], su(bp + (wm*(MT*16) + mi*16 + arow)*24 + acol));
        #pragma unroll
        for (int ni=0; ni<4; ni++) {
            int cc = wn*32 + ni*8;
            ldsm_x2t(fwh[ni], su(bp + 3072 + brow*BROW + cc));
            ldsm_x2t(fwl[ni], su(bp + 3072 + BSZ + brow*BROW + cc));
        }
        #pragma unroll
        for (int mi=0; mi<MT; mi++)
            #pragma unroll
            for (int ni=0; ni<4; ni++) {
                mma_f16(acc[mi][ni], fa[mi], fwh[ni]);
                mma_f16(acc[mi][ni], fa[mi], fwl[ni]);
            }
    }

    float* Hb = hsel ? g_H1 : g_H0;
    #pragma unroll
    for (int mi=0; mi<MT; mi++)
        #pragma unroll
        for (int ni=0; ni<4; ni++) {
            long rb = row0 + wm*(MT*16) + mi*16 + (lane >> 2);
            int  cb = wn*32 + ni*8 + 2*(lane & 3);
            #pragma unroll
            for (int e=0; e<4; e++) {
                long row = rb + ((e >= 2) ? 8 : 0);
                int  c   = cb + (e & 1);
                float v = acc[mi][ni][e] + bias[c];
                if (MODE == 0) {
                    g_UR[row*128 + c] = 1.f/(1.f + expf(-v));
                } else {
                    float cv = tanhf(v);
                    float u  = g_UR[row*128 + c];
                    float h  = Hb[row*64 + c];
                    Hb[row*64 + c] = (1.f - u)*h + u*cv;
                }
            }
        }
}

// ---------------- decoder memory attention + output projection ----------------
__global__ void query_kernel(const float* __restrict__ Wa) {
    int b = blockIdx.x, tid = threadIdx.x;
    float p[8];
    #pragma unroll
    for (int d = 0; d < 8; d++) p[d] = 0.f;
    for (int idx = tid; idx < N_*H_; idx += 256) {
        int n = idx >> 6, j = idx & 63;
        float v = g_H1[(long)(n*B_ + b)*64 + j];
        const float* w = Wa + (long)idx*8;
        #pragma unroll
        for (int d = 0; d < 8; d++) p[d] += v*w[d];
    }
    #pragma unroll
    for (int d = 0; d < 8; d++)
        for (int off = 16; off > 0; off >>= 1) p[d] += __shfl_down_sync(0xffffffffu, p[d], off);
    __shared__ float sm[8][8];
    int w = tid >> 5, l = tid & 31;
    if (l == 0) { for (int d = 0; d < 8; d++) sm[w][d] = p[d]; }
    __syncthreads();
    if (tid < 8) {
        float s = 0.f;
        for (int ww = 0; ww < 8; ww++) s += sm[ww][tid];
        g_Q[b*8 + tid] = s;
    }
}

__global__ void attm_kernel(const float* __restrict__ mem, const float* __restrict__ fcw) {
    int b = blockIdx.x, tid = threadIdx.x;
    __shared__ float am[8];
    if (tid == 0) {
        float q[8];
        for (int d = 0; d < 8; d++) q[d] = g_Q[b*8 + d];
        float s[4]; float mx = -1e30f;
        for (int m = 0; m < 4; m++) {
            float a = 0.f;
            for (int d = 0; d < 8; d++) a += q[d]*mem[m*8 + d];
            s[m] = a; mx = fmaxf(mx, a);
        }
        float den = 0.f;
        for (int m = 0; m < 4; m++) { s[m] = expf(s[m]-mx); den += s[m]; }
        for (int d = 0; d < 8; d++) {
            float a = 0.f;
            for (int m = 0; m < 4; m++) a += (s[m]/den)*mem[m*8 + d];
            am[d] = a;
        }
    }
    __syncthreads();
    for (int i = tid; i < N_*8; i += 256) {
        float s = 0.f;
        #pragma unroll
        for (int d = 0; d < 8; d++) s += am[d]*fcw[(long)d*(N_*8) + i];
        g_ATTM[(long)b*(N_*8) + i] = s;
    }
}

__global__ void out_kernel(const float* __restrict__ pW, const float* __restrict__ pb,
                           float* __restrict__ outp, int s) {
    int row = blockIdx.x*256 + threadIdx.x;
    if (row >= NB) return;
    int b = row % B_, n = row / B_;
    float a0 = pb[0], a1 = pb[1];
    const float* h = g_H1 + (long)row*64;
    #pragma unroll
    for (int j = 0; j < 64; j++) { float v = h[j]; a0 += v*pW[j*2]; a1 += v*pW[j*2+1]; }
    const float* at = g_ATTM + (long)b*(N_*8) + n*8;
    #pragma unroll
    for (int d = 0; d < 8; d++) { float v = at[d]; a0 += v*pW[(64+d)*2]; a1 += v*pW[(64+d)*2+1]; }
    a0 = fmaxf(a0, 0.f); a1 = fmaxf(a1, 0.f);
    g_GO[row*2] = a0; g_GO[row*2+1] = a1;
    long o = ((long)(b*HOR_ + s)*N_ + n)*CIN_;
    outp[o] = a0; outp[o+1] = a1;
}

// ---------------- orchestration ----------------
extern "C" void kernel_launch(void* const* d_in, const int* in_sizes, int n_in,
                              void* d_out, int out_size) {
    (void)in_sizes; (void)n_in; (void)out_size;
    const float* x_seq = (const float*)d_in[0];
    const float* t_x   = (const float*)d_in[1];
    const float* t_y   = (const float*)d_in[2];
    const float* G     = (const float*)d_in[3];
    const float* eWg0  = (const float*)d_in[4];  const float* ebg0 = (const float*)d_in[5];
    const float* eWc0  = (const float*)d_in[6];  const float* ebc0 = (const float*)d_in[7];
    const float* eWg1  = (const float*)d_in[8];  const float* ebg1 = (const float*)d_in[9];
    const float* eWc1  = (const float*)d_in[10]; const float* ebc1 = (const float*)d_in[11];
    const float* dWg0  = (const float*)d_in[12]; const float* dbg0 = (const float*)d_in[13];
    const float* dWc0  = (const float*)d_in[14]; const float* dbc0 = (const float*)d_in[15];
    const float* dWg1  = (const float*)d_in[16]; const float* dbg1 = (const float*)d_in[17];
    const float* dWc1  = (const float*)d_in[18]; const float* dbc1 = (const float*)d_in[19];
    const float* mW1   = (const float*)d_in[20]; const float* mb1  = (const float*)d_in[21];
    const float* mW2   = (const float*)d_in[22]; const float* mb2  = (const float*)d_in[23];
    const float* mem   = (const float*)d_in[24];
    const float* Wa    = (const float*)d_in[25];
    const float* fcw   = (const float*)d_in[26];
    const float* projW = (const float*)d_in[27];
    const float* projb = (const float*)d_in[28];
    float* outp = (float*)d_out;

    const int PROP_SMEM    = 3*P_STG*2;                  // 49920 B
    const int PROJ128_SMEM = 3*(3072 + 2*16*136)*2;      // 44544 B
    const int PROJ64_SMEM  = 3*(3072 + 2*16*72)*2;       // 32256 B
    cudaFuncSetAttribute(prop_tc, cudaFuncAttributeMaxDynamicSharedMemorySize, PROP_SMEM);
    cudaFuncSetAttribute(proj_tc<128,0>, cudaFuncAttributeMaxDynamicSharedMemorySize, PROJ128_SMEM);
    cudaFuncSetAttribute(proj_tc<64,1>, cudaFuncAttributeMaxDynamicSharedMemorySize, PROJ64_SMEM);

    transpose_kernel<<<dim3(25,25), dim3(32,32)>>>(G);
    g2_kernel<<<dim3(7,7), 256>>>();
    split_a2<<<(MPAD*800+255)/256, 256>>>();

    auto fold = [](const float* W, int isGate, int widx, int P, int O) {
        int KT = ((3*P + 15)/16)*16;
        fold_split<<<(KT*O+255)/256, 256>>>(W, isGate, widx, P, O, KT);
    };
    fold(eWg0,1,0,68,128);  fold(eWc0,0,0,68,64);
    fold(eWg1,1,1,128,128); fold(eWc1,0,1,128,64);
    fold(dWg0,1,2,68,128);  fold(dWc0,0,2,68,64);
    fold(dWg1,1,3,128,128); fold(dWc1,0,3,128,64);

    mlp_kernel<<<B_*T_,   256>>>(t_x, mW1, mb1, mW2, mb2, 0);
    mlp_kernel<<<B_*HOR_, 256>>>(t_y, mW1, mb1, mW2, mb2, 1);
    zero_state<<<(NB*H_+255)/256, 256>>>();

    auto cell0 = [&](int wsel, const float* bg, const float* bc) {
        prop_tc<<<dim3(34,13), 256, PROP_SMEM>>>(0, CF0, 0, 68, 136, 68);
        proj_tc<128,0><<<NB/128, 256, PROJ128_SMEM>>>(0, CF0, 208, wsel, bg, 0);
        build_fc0<<<(NB*76+255)/256, 256>>>();
        prop_tc<<<dim3(32,13), 256, PROP_SMEM>>>(1, CF0, 4, 72, 140, 64);
        proj_tc<64,1><<<NB/128, 256, PROJ64_SMEM>>>(1, CF0, 208, wsel, bc, 0);
    };
    auto cell1 = [&](int wsel, const float* bg, const float* bc) {
        prop_tc<<<dim3(64,13), 256, PROP_SMEM>>>(0, CF1, 0, 128, 256, 128);
        proj_tc<128,0><<<NB/128, 256, PROJ128_SMEM>>>(0, CF1, 384, wsel, bg, 1);
        build_rh1<<<(NB*64+255)/256, 256>>>();
        prop_tc<<<dim3(32,13), 256, PROP_SMEM>>>(1, CF1, 64, 192, 320, 64);
        proj_tc<64,1><<<NB/128, 256, PROJ64_SMEM>>>(2, CF1, 384, wsel, bc, 1);
    };

    // encoder
    for (int t = 0; t < T_; t++) {
        build_xh0<<<(NB*68+255)/256, 256>>>(x_seq, t, 0);
        cell0(0, ebg0, ebc0);
        build_xh1<<<(NB*128+255)/256, 256>>>();
        cell1(1, ebg1, ebc1);
    }
    // decoder
    for (int s = 0; s < HOR_; s++) {
        build_xh0<<<(NB*68+255)/256, 256>>>(x_seq, s, 1);
        cell0(2, dbg0, dbc0);
        build_xh1<<<(NB*128+255)/256, 256>>>();
        cell1(3, dbg1, dbc1);
        query_kernel<<<B_, 256>>>(Wa);
        attm_kernel<<<B_, 256>>>(mem, fcw);
        out_kernel<<<NB/256, 256>>>(projW, projb, outp, s);
    }
}